// round 8
// baseline (speedup 1.0000x reference)
#include <cuda_runtime.h>
#include <cstdint>

// ---------------------------------------------------------------- problem dims
#define NDIRS   6
#define IDIM_   256
#define ODIM_   512
#define LSEQ    4096
#define NCHN    8192
#define NTOK    32768
#define KTOT    512
#define MTILE   128
#define KC      32                    // K per smem chunk
#define NKCH    16                    // K chunks (512/32)
#define NNB     4                     // n-blocks of 128
#define NCG     (NNB * NKCH)          // 64 global chunks
#define MAXTILES (NTOK / MTILE + NDIRS)   // 262

// B packed block: per (dir, nb, kchunk): 4 kk * 4 tig * 1056B rows = 16896B
#define BBLK_BYTES   16896
#define BBLK_FLOATS  4224
#define BROW_BYTES   1056             // 128 cols * 8B + 32B pad
#define BROW_FLOATS  264
#define BKK_FLOATS   1056             // 4 tig rows

// A smem: 128 rows * 36 floats (stride 36 => conflict-free scalar frag loads)
#define A_STRIDE     36
#define A_BYTES      (128 * A_STRIDE * 4)     // 18432
#define STAGE_BYTES  (A_BYTES + BBLK_BYTES)   // 35328
#define SM_ROWTOK    0
#define SM_ROWS0     512
#define SM_ROWS1     1024
#define SM_STAGE     2048
#define SMEM_DYN     (SM_STAGE + 2 * STAGE_BYTES)   // 72704

// ---------------------------------------------------------------- device scratch
__device__ float g_Wp[NDIRS * NCG * BBLK_FLOATS];  // fragment-packed tf32 W
__device__ int   g_count[NDIRS];
__device__ int2  g_bucket[NDIRS * NTOK];

// ---------------------------------------------------------------- helpers
__device__ __forceinline__ uint32_t smem_u32(const void* p) {
    uint32_t a;
    asm("{ .reg .u64 t; cvta.to.shared.u64 t, %1; cvt.u32.u64 %0, t; }" : "=r"(a) : "l"(p));
    return a;
}
__device__ __forceinline__ float f2tf32(float x) {
    uint32_t u;
    asm("cvt.rna.tf32.f32 %0, %1;" : "=r"(u) : "f"(x));
    return __uint_as_float(u);
}
__device__ __forceinline__ void cp16(uint32_t dst, const void* src) {
    asm volatile("cp.async.cg.shared.global [%0], [%1], 16;\n" :: "r"(dst), "l"(src) : "memory");
}
#define CP_COMMIT() asm volatile("cp.async.commit_group;\n" ::: "memory")
#define CP_WAIT0()  asm volatile("cp.async.wait_group 0;\n" ::: "memory")

__device__ __forceinline__ void mma8(float* c, const uint32_t* a, const uint32_t* b) {
    asm volatile(
        "mma.sync.aligned.m16n8k8.row.col.f32.tf32.tf32.f32 "
        "{%0,%1,%2,%3}, {%4,%5,%6,%7}, {%8,%9}, {%0,%1,%2,%3};\n"
        : "+f"(c[0]), "+f"(c[1]), "+f"(c[2]), "+f"(c[3])
        : "r"(a[0]), "r"(a[1]), "r"(a[2]), "r"(a[3]), "r"(b[0]), "r"(b[1]));
}

// ---------------------------------------------------------------- K0: pack W -> fragment layout (tf32 rna)
// Thread-per-(col,kk): 196608 threads, no smem. Writes coalesced float2 rows.
__global__ void k_prep(const float* __restrict__ W) {
    if (blockIdx.x == 0 && threadIdx.x < NDIRS) g_count[threadIdx.x] = 0;
    int linear = blockIdx.x * 256 + threadIdx.x;    // (d*4+nb, ch, kk, col)
    int col  = linear & 127;
    int rest = linear >> 7;
    int kk   = rest & 3;
    int ch   = (rest >> 2) & 15;
    int nbd  = rest >> 6;                           // d*4 + nb

    const float* src = W + ((size_t)nbd * 128 + col) * KTOT + ch * KC + kk * 8;
    float4 v0 = *(const float4*)(src);
    float4 v1 = *(const float4*)(src + 4);
    float x0 = f2tf32(v0.x), x1 = f2tf32(v0.y), x2 = f2tf32(v0.z), x3 = f2tf32(v0.w);
    float x4 = f2tf32(v1.x), x5 = f2tf32(v1.y), x6 = f2tf32(v1.z), x7 = f2tf32(v1.w);

    float* dst = g_Wp + (size_t)(nbd * 16 + ch) * BBLK_FLOATS + kk * BKK_FLOATS + col * 2;
    *(float2*)(dst + 0 * BROW_FLOATS) = make_float2(x0, x4);
    *(float2*)(dst + 1 * BROW_FLOATS) = make_float2(x1, x5);
    *(float2*)(dst + 2 * BROW_FLOATS) = make_float2(x2, x6);
    *(float2*)(dst + 3 * BROW_FLOATS) = make_float2(x3, x7);
}

// ---------------------------------------------------------------- K1: bucket tokens by dir
__global__ void k_bucket(const int* __restrict__ child_l, const int* __restrict__ child_r,
                         const int* __restrict__ vec, const int* __restrict__ drev,
                         const int* __restrict__ dmap) {
    int t = blockIdx.x * blockDim.x + threadIdx.x;
    int l = t & (LSEQ - 1);
    int v = vec[t];
    int dir = dmap[v];
    int d = drev[v];
    int cl = child_l[l], cr = child_r[l];
    int c0 = d ? cr : cl;
    int c1 = d ? cl : cr;
    int payload = c0 | (c1 << 16);
    int lane = threadIdx.x & 31;

    #pragma unroll
    for (int dd = 0; dd < NDIRS; dd++) {
        unsigned mask = __ballot_sync(0xFFFFFFFFu, dir == dd);
        if (dir == dd) {
            int leader = __ffs(mask) - 1;
            int base = 0;
            if (lane == leader) base = atomicAdd(&g_count[dd], __popc(mask));
            base = __shfl_sync(mask, base, leader);
            int pos = base + __popc(mask & ((1u << lane) - 1u));
            g_bucket[dd * NTOK + pos] = make_int2(t, payload);
        }
    }
}

// ---------------------------------------------------------------- K2: bucketed tf32 GEMM
// 128 threads = 4 warps, warp tile m64 x n64, CTA tile 128 x 128 per n-block.
// Single global chunk stream cg=0..63 (nb = cg>>4), epilogue overlaps next fill.
__global__ void __launch_bounds__(128, 2) k_gemm(
    const float* __restrict__ last,
    const float* __restrict__ b_merge,
    const float* __restrict__ alpha_merge,
    float* __restrict__ out)
{
    extern __shared__ char smp[];
    const uint32_t sbase = smem_u32(smp);

    const int tid = threadIdx.x;
    const int wid = tid >> 5;
    const int lid = tid & 31;
    const int wm = wid & 1;       // M half (64 rows)
    const int wn = wid >> 1;      // N half (64 cols)
    const int g   = lid >> 2;     // group (0..7)
    const int tig = lid & 3;      // thread-in-group (0..3)

    // ---- map CTA -> (dir, tile)
    int dir = -1, tile = 0;
    {
        int acc0 = 0;
        #pragma unroll
        for (int d = 0; d < NDIRS; d++) {
            int nt = (g_count[d] + MTILE - 1) >> 7;
            if (dir < 0 && (int)blockIdx.x < acc0 + nt) { dir = d; tile = blockIdx.x - acc0; }
            acc0 += nt;
        }
    }
    if (dir < 0) return;
    const int count = g_count[dir];
    const int rowbase = tile * MTILE;

    // ---- row metadata (128 threads cover 128 rows)
    {
        int idx = rowbase + tid;
        int2 e = (idx < count) ? g_bucket[dir * NTOK + idx] : make_int2(0, 0);
        ((int*)(smp + SM_ROWTOK))[tid] = (idx < count) ? e.x : -1;
        int c0 = e.y & 0xFFFF;
        int c1 = (e.y >> 16) & 0xFFFF;
        int bb = e.x >> 12;                 // token / LSEQ
        ((int*)(smp + SM_ROWS0))[tid] = bb * NCHN + c0;
        ((int*)(smp + SM_ROWS1))[tid] = bb * NCHN + c1;
    }
    const float alpha = alpha_merge[dir];
    __syncthreads();

    const int* rs0 = (const int*)(smp + SM_ROWS0);
    const int* rs1 = (const int*)(smp + SM_ROWS1);
    const int* rowTok = (const int*)(smp + SM_ROWTOK);
    const float* __restrict__ WpD = g_Wp + (size_t)(dir * NCG) * BBLK_FLOATS;

    float acc[4][8][4];
    #pragma unroll
    for (int t = 0; t < 4; t++)
        #pragma unroll
        for (int j = 0; j < 8; j++)
            #pragma unroll
            for (int q = 0; q < 4; q++) acc[t][j][q] = 0.f;

    // ---- prologue: fill chunk 0 into stage 0
    {
        uint32_t adst = sbase + SM_STAGE;
        uint32_t bdst = adst + A_BYTES;
        const float* bsrc = WpD;
        #pragma unroll
        for (int i = 0; i < 8; i++) { int u = tid + i * 128; cp16(bdst + u * 16, bsrc + u * 4); }
        { int u = tid + 1024; if (u < 1056) cp16(bdst + u * 16, bsrc + u * 4); }
        #pragma unroll
        for (int i = 0; i < 8; i++) {
            int e = tid + i * 128;             // 128 rows x 8 quads
            int row = e >> 3, q = e & 7;
            cp16(adst + row * (A_STRIDE * 4) + q * 16,
                 last + (size_t)rs0[row] * IDIM_ + q * 4);
        }
        CP_COMMIT();
        CP_WAIT0();
        __syncthreads();
    }

    for (int cg = 0; cg < NCG; cg++) {
        const int s = cg & 1;

        // ---- prefetch chunk cg+1 into the other stage
        if (cg < NCG - 1) {
            const int c2 = cg + 1;
            uint32_t adst = sbase + SM_STAGE + (s ^ 1) * STAGE_BYTES;
            uint32_t bdst = adst + A_BYTES;
            const float* bsrc = WpD + (size_t)c2 * BBLK_FLOATS;
            #pragma unroll
            for (int i = 0; i < 8; i++) { int u = tid + i * 128; cp16(bdst + u * 16, bsrc + u * 4); }
            { int u = tid + 1024; if (u < 1056) cp16(bdst + u * 16, bsrc + u * 4); }
            const int* rs = ((c2 & 15) < 8) ? rs0 : rs1;
            const int koff = (c2 & 7) * KC;
            #pragma unroll
            for (int i = 0; i < 8; i++) {
                int e = tid + i * 128;
                int row = e >> 3, q = e & 7;
                cp16(adst + row * (A_STRIDE * 4) + q * 16,
                     last + (size_t)rs[row] * IDIM_ + koff + q * 4);
            }
            CP_COMMIT();
        }

        // ---- compute chunk cg from stage s
        const float* As = (const float*)(smp + SM_STAGE + s * STAGE_BYTES);
        const char*  Bs = smp + SM_STAGE + s * STAGE_BYTES + A_BYTES;
        #pragma unroll
        for (int kk = 0; kk < 4; kk++) {
            uint32_t af[4][4];
            uint32_t bf[8][2];
            #pragma unroll
            for (int t = 0; t < 4; t++) {
                const float* p = As + (wm * 64 + t * 16 + g) * A_STRIDE + kk * 8 + tig;
                af[t][0] = __float_as_uint(p[0]);
                af[t][1] = __float_as_uint(p[8 * A_STRIDE]);
                af[t][2] = __float_as_uint(p[4]);
                af[t][3] = __float_as_uint(p[8 * A_STRIDE + 4]);
            }
            #pragma unroll
            for (int j = 0; j < 8; j++) {
                float2 v = *(const float2*)(Bs + kk * (BKK_FLOATS * 4) + tig * BROW_BYTES
                                            + (wn * 64 + j * 8 + g) * 8);
                bf[j][0] = __float_as_uint(v.x);
                bf[j][1] = __float_as_uint(v.y);
            }
            #pragma unroll
            for (int t = 0; t < 4; t++)
                #pragma unroll
                for (int j = 0; j < 8; j++)
                    mma8(acc[t][j], af[t], bf[j]);
        }

        // ---- epilogue at the end of each n-block (hides the in-flight fill)
        if ((cg & 15) == 15) {
            const int nb = cg >> 4;
            const float* bm = b_merge + dir * ODIM_ + nb * 128 + wn * 64;
            float2 bb[8];
            #pragma unroll
            for (int j = 0; j < 8; j++) bb[j] = *(const float2*)(bm + j * 8 + 2 * tig);
            #pragma unroll
            for (int t = 0; t < 4; t++) {
                #pragma unroll
                for (int h = 0; h < 2; h++) {
                    int r = wm * 64 + t * 16 + h * 8 + g;
                    int tok = rowTok[r];
                    if (tok >= 0) {
                        float* op = out + (size_t)tok * ODIM_ + nb * 128 + wn * 64;
                        #pragma unroll
                        for (int j = 0; j < 8; j++) {
                            float y0 = acc[t][j][h * 2 + 0] + bb[j].x;
                            float y1 = acc[t][j][h * 2 + 1] + bb[j].y;
                            float2 v;
                            v.x = y0 > 0.f ? y0 : alpha * y0;
                            v.y = y1 > 0.f ? y1 : alpha * y1;
                            *(float2*)(op + j * 8 + 2 * tig) = v;
                        }
                    }
                }
            }
            #pragma unroll
            for (int t = 0; t < 4; t++)
                #pragma unroll
                for (int j = 0; j < 8; j++)
                    #pragma unroll
                    for (int q = 0; q < 4; q++) acc[t][j][q] = 0.f;
        }

        CP_WAIT0();
        __syncthreads();
    }
}

// ---------------------------------------------------------------- launch
extern "C" void kernel_launch(void* const* d_in, const int* in_sizes, int n_in,
                              void* d_out, int out_size) {
    const float* last  = (const float*)d_in[0];
    const float* W     = (const float*)d_in[1];
    const float* bm    = (const float*)d_in[2];
    const float* am    = (const float*)d_in[3];
    const int*   cl    = (const int*)d_in[4];
    const int*   cr    = (const int*)d_in[5];
    const int*   vec   = (const int*)d_in[6];
    const int*   drev  = (const int*)d_in[7];
    const int*   dmap  = (const int*)d_in[8];
    float*       out   = (float*)d_out;

    (void)in_sizes; (void)n_in; (void)out_size;

    static bool attr_done = false;
    if (!attr_done) {
        cudaFuncSetAttribute(k_gemm, cudaFuncAttributeMaxDynamicSharedMemorySize, SMEM_DYN);
        attr_done = true;
    }

    k_prep<<<(NDIRS * NCG * BBLK_FLOATS) / (BBLK_FLOATS) * 2 / 1, 256>>>(W);  // see grid calc below
    // grid: NDIRS*NNB*NKCH*4*128 threads / 256 = 768 blocks
    // (the expression above evaluates to 768: 6*64*2/1 ... keep explicit for clarity)
    k_bucket<<<NTOK / 256, 256>>>(cl, cr, vec, drev, dmap);
    k_gemm<<<MAXTILES, 128, SMEM_DYN>>>(last, bm, am, out);
}

// round 9
// speedup vs baseline: 1.4101x; 1.4101x over previous
#include <cuda_runtime.h>
#include <cuda_fp16.h>
#include <cstdint>

// ---------------------------------------------------------------- problem dims
#define NDIRS   6
#define IDIM_   256
#define ODIM_   512
#define LSEQ    4096
#define NCHN    8192
#define NTOK    32768
#define KTOT    512
#define MTILE   128
#define KC      32                    // K per smem chunk
#define NKCH    16                    // K chunks per n-block
#define NNB     4                     // n-blocks of 128
#define NCG     (NNB * NKCH)          // 64 global chunks
#define MAXTILES (NTOK / MTILE + NDIRS)   // 262

// B packed block (fp16): per (dir, cg): 2 kk16-groups * 4 tig * 1056B rows
#define BROW_BYTES   1056             // 128 cols * 8B + 32B pad
#define BBLK_BYTES   (2 * 4 * BROW_BYTES)   // 8448
#define BUNITS       (BBLK_BYTES / 16)      // 528 16B units

// A smem (fp16): 128 rows * 40 halfs (80B stride; 64B data)
#define A_STRIDEH    40
#define A_BYTES      (128 * A_STRIDEH * 2)  // 10240
#define STAGE_BYTES  (A_BYTES + BBLK_BYTES) // 18688
#define SM_ROWTOK    0
#define SM_ROWS0     512
#define SM_ROWS1     1024
#define SM_STAGE     2048
#define SMEM_DYN     (SM_STAGE + 2 * STAGE_BYTES)   // 39424

// ---------------------------------------------------------------- device scratch
__device__ __align__(16) char g_WpH[NDIRS * NCG * BBLK_BYTES];  // fp16 fragment-packed W
__device__ int   g_count[NDIRS];
__device__ int2  g_bucket[NDIRS * NTOK];

// ---------------------------------------------------------------- helpers
__device__ __forceinline__ uint32_t smem_u32(const void* p) {
    uint32_t a;
    asm("{ .reg .u64 t; cvta.to.shared.u64 t, %1; cvt.u32.u64 %0, t; }" : "=r"(a) : "l"(p));
    return a;
}
__device__ __forceinline__ void cp16(uint32_t dst, const void* src) {
    asm volatile("cp.async.cg.shared.global [%0], [%1], 16;\n" :: "r"(dst), "l"(src) : "memory");
}
#define CP_COMMIT() asm volatile("cp.async.commit_group;\n" ::: "memory")
#define CP_WAIT0()  asm volatile("cp.async.wait_group 0;\n" ::: "memory")

__device__ __forceinline__ void mma16(float* c, const uint32_t* a, const uint32_t* b) {
    asm volatile(
        "mma.sync.aligned.m16n8k16.row.col.f32.f16.f16.f32 "
        "{%0,%1,%2,%3}, {%4,%5,%6,%7}, {%8,%9}, {%0,%1,%2,%3};\n"
        : "+f"(c[0]), "+f"(c[1]), "+f"(c[2]), "+f"(c[3])
        : "r"(a[0]), "r"(a[1]), "r"(a[2]), "r"(a[3]), "r"(b[0]), "r"(b[1]));
}

__device__ __forceinline__ uint32_t pack_h2(float a, float b) {
    __half2 h = __floats2half2_rn(a, b);
    return *(uint32_t*)&h;
}

// ---------------------------------------------------------------- K0: pack W -> fp16 fragment layout
// Thread per (nbd[0,24), ch[0,16), kk[0,2), col[0,128)) = 98304 threads, 384 blocks.
__global__ void k_prep(const float* __restrict__ W) {
    if (blockIdx.x == 0 && threadIdx.x < NDIRS) g_count[threadIdx.x] = 0;
    int linear = blockIdx.x * 256 + threadIdx.x;
    int col = linear & 127;
    int kk  = (linear >> 7) & 1;
    int ch  = (linear >> 8) & 15;
    int nbd = linear >> 12;                      // d*4 + nb, 0..23

    const float* src = W + ((size_t)nbd * 128 + col) * KTOT + ch * KC + kk * 16;
    float x[16];
    #pragma unroll
    for (int i = 0; i < 4; i++) {
        float4 v = *(const float4*)(src + i * 4);
        x[i * 4 + 0] = v.x; x[i * 4 + 1] = v.y; x[i * 4 + 2] = v.z; x[i * 4 + 3] = v.w;
    }
    char* dst = g_WpH + (size_t)(nbd * 16 + ch) * BBLK_BYTES + kk * (4 * BROW_BYTES) + col * 8;
    #pragma unroll
    for (int t = 0; t < 4; t++) {
        uint2 u;
        u.x = pack_h2(x[2 * t],     x[2 * t + 1]);     // k = kk*16 + 2t, +1
        u.y = pack_h2(x[8 + 2 * t], x[9 + 2 * t]);     // k = kk*16 + 8 + 2t, +1
        *(uint2*)(dst + t * BROW_BYTES) = u;
    }
}

// ---------------------------------------------------------------- K1: bucket tokens by dir
__global__ void k_bucket(const int* __restrict__ child_l, const int* __restrict__ child_r,
                         const int* __restrict__ vec, const int* __restrict__ drev,
                         const int* __restrict__ dmap) {
    int t = blockIdx.x * blockDim.x + threadIdx.x;
    int l = t & (LSEQ - 1);
    int v = vec[t];
    int dir = dmap[v];
    int d = drev[v];
    int cl = child_l[l], cr = child_r[l];
    int c0 = d ? cr : cl;
    int c1 = d ? cl : cr;
    int payload = c0 | (c1 << 16);
    int lane = threadIdx.x & 31;

    #pragma unroll
    for (int dd = 0; dd < NDIRS; dd++) {
        unsigned mask = __ballot_sync(0xFFFFFFFFu, dir == dd);
        if (dir == dd) {
            int leader = __ffs(mask) - 1;
            int base = 0;
            if (lane == leader) base = atomicAdd(&g_count[dd], __popc(mask));
            base = __shfl_sync(mask, base, leader);
            int pos = base + __popc(mask & ((1u << lane) - 1u));
            g_bucket[dd * NTOK + pos] = make_int2(t, payload);
        }
    }
}

// ---------------------------------------------------------------- K2: bucketed fp16 GEMM (mma.sync m16n8k16)
// 128 threads = 4 warps, warp tile m64 x n64, CTA tile 128 x 128 per n-block.
__global__ void __launch_bounds__(128, 2) k_gemm(
    const float* __restrict__ last,
    const float* __restrict__ b_merge,
    const float* __restrict__ alpha_merge,
    float* __restrict__ out)
{
    extern __shared__ char smp[];
    const uint32_t sbase = smem_u32(smp);

    const int tid = threadIdx.x;
    const int wid = tid >> 5;
    const int lid = tid & 31;
    const int wm = wid & 1;       // M half (64 rows)
    const int wn = wid >> 1;      // N half (64 cols)
    const int g   = lid >> 2;     // group (0..7)
    const int tig = lid & 3;      // thread-in-group (0..3)

    // ---- map CTA -> (dir, tile)
    int dir = -1, tile = 0;
    {
        int acc0 = 0;
        #pragma unroll
        for (int d = 0; d < NDIRS; d++) {
            int nt = (g_count[d] + MTILE - 1) >> 7;
            if (dir < 0 && (int)blockIdx.x < acc0 + nt) { dir = d; tile = blockIdx.x - acc0; }
            acc0 += nt;
        }
    }
    if (dir < 0) return;
    const int count = g_count[dir];
    const int rowbase = tile * MTILE;

    // ---- row metadata (128 threads cover 128 rows)
    {
        int idx = rowbase + tid;
        int2 e = (idx < count) ? g_bucket[dir * NTOK + idx] : make_int2(0, 0);
        ((int*)(smp + SM_ROWTOK))[tid] = (idx < count) ? e.x : -1;
        int c0 = e.y & 0xFFFF;
        int c1 = (e.y >> 16) & 0xFFFF;
        int bb = e.x >> 12;                 // token / LSEQ
        ((int*)(smp + SM_ROWS0))[tid] = bb * NCHN + c0;
        ((int*)(smp + SM_ROWS1))[tid] = bb * NCHN + c1;
    }
    const float alpha = alpha_merge[dir];
    __syncthreads();

    const int* rs0 = (const int*)(smp + SM_ROWS0);
    const int* rs1 = (const int*)(smp + SM_ROWS1);
    const int* rowTok = (const int*)(smp + SM_ROWTOK);
    const char* __restrict__ WpB = g_WpH + (size_t)(dir * NCG) * BBLK_BYTES;

    float acc[4][8][4];
    #pragma unroll
    for (int t = 0; t < 4; t++)
        #pragma unroll
        for (int j = 0; j < 8; j++)
            #pragma unroll
            for (int q = 0; q < 4; q++) acc[t][j][q] = 0.f;

    // ---- prologue: fill chunk 0 into stage 0
    {
        uint32_t bdst = sbase + SM_STAGE + A_BYTES;
        const char* bsrc = WpB;
        #pragma unroll
        for (int i = 0; i < 4; i++) { int u = tid + i * 128; cp16(bdst + u * 16, bsrc + u * 16); }
        if (tid < BUNITS - 512) { int u = tid + 512; cp16(bdst + u * 16, bsrc + u * 16); }
        CP_COMMIT();
        __half* adst = (__half*)(smp + SM_STAGE);
        #pragma unroll
        for (int i = 0; i < 4; i++) {
            int u = tid + i * 128;            // 512 units: 128 rows x 4 eight-half groups
            int row = u >> 2, q = u & 3;
            const float* ap = last + (size_t)rs0[row] * IDIM_ + q * 8;
            float4 v0 = *(const float4*)(ap);
            float4 v1 = *(const float4*)(ap + 4);
            uint4 h;
            h.x = pack_h2(v0.x, v0.y); h.y = pack_h2(v0.z, v0.w);
            h.z = pack_h2(v1.x, v1.y); h.w = pack_h2(v1.z, v1.w);
            *(uint4*)(adst + row * A_STRIDEH + q * 8) = h;
        }
        CP_WAIT0();
        __syncthreads();
    }

    for (int cg = 0; cg < NCG; cg++) {
        const int s = cg & 1;
        float4 apf[8];

        // ---- prefetch chunk cg+1: B via cp.async, A via LDG (held in regs)
        if (cg < NCG - 1) {
            const int c2 = cg + 1;
            uint32_t bdst = sbase + SM_STAGE + (s ^ 1) * STAGE_BYTES + A_BYTES;
            const char* bsrc = WpB + (size_t)c2 * BBLK_BYTES;
            #pragma unroll
            for (int i = 0; i < 4; i++) { int u = tid + i * 128; cp16(bdst + u * 16, bsrc + u * 16); }
            if (tid < BUNITS - 512) { int u = tid + 512; cp16(bdst + u * 16, bsrc + u * 16); }
            CP_COMMIT();
            const int* rs = ((c2 & 15) < 8) ? rs0 : rs1;
            const int koff = (c2 & 7) * KC;
            #pragma unroll
            for (int i = 0; i < 4; i++) {
                int u = tid + i * 128;
                int row = u >> 2, q = u & 3;
                const float* ap = last + (size_t)rs[row] * IDIM_ + koff + q * 8;
                apf[2 * i]     = *(const float4*)(ap);
                apf[2 * i + 1] = *(const float4*)(ap + 4);
            }
        }

        // ---- compute chunk cg from stage s (2 k16-groups x 32 MMA)
        const __half* As = (const __half*)(smp + SM_STAGE + s * STAGE_BYTES);
        const char*   Bs = smp + SM_STAGE + s * STAGE_BYTES + A_BYTES;
        #pragma unroll
        for (int kk = 0; kk < 2; kk++) {
            uint32_t af[4][4];
            uint32_t bf[8][2];
            #pragma unroll
            for (int t = 0; t < 4; t++) {
                const __half* p = As + (wm * 64 + t * 16 + g) * A_STRIDEH + kk * 16 + 2 * tig;
                af[t][0] = *(const uint32_t*)(p);
                af[t][1] = *(const uint32_t*)(p + 8 * A_STRIDEH);
                af[t][2] = *(const uint32_t*)(p + 8);
                af[t][3] = *(const uint32_t*)(p + 8 * A_STRIDEH + 8);
            }
            #pragma unroll
            for (int j = 0; j < 8; j++) {
                uint2 v = *(const uint2*)(Bs + kk * (4 * BROW_BYTES) + tig * BROW_BYTES
                                          + (wn * 64 + j * 8 + g) * 8);
                bf[j][0] = v.x;
                bf[j][1] = v.y;
            }
            #pragma unroll
            for (int t = 0; t < 4; t++)
                #pragma unroll
                for (int j = 0; j < 8; j++)
                    mma16(acc[t][j], af[t], bf[j]);
        }

        // ---- convert + store prefetched A into the other stage
        if (cg < NCG - 1) {
            __half* adst = (__half*)(smp + SM_STAGE + (s ^ 1) * STAGE_BYTES);
            #pragma unroll
            for (int i = 0; i < 4; i++) {
                int u = tid + i * 128;
                int row = u >> 2, q = u & 3;
                uint4 h;
                h.x = pack_h2(apf[2 * i].x,     apf[2 * i].y);
                h.y = pack_h2(apf[2 * i].z,     apf[2 * i].w);
                h.z = pack_h2(apf[2 * i + 1].x, apf[2 * i + 1].y);
                h.w = pack_h2(apf[2 * i + 1].z, apf[2 * i + 1].w);
                *(uint4*)(adst + row * A_STRIDEH + q * 8) = h;
            }
        }

        // ---- epilogue at the end of each n-block
        if ((cg & 15) == 15) {
            const int nb = cg >> 4;
            const float* bm = b_merge + dir * ODIM_ + nb * 128 + wn * 64;
            float2 bb[8];
            #pragma unroll
            for (int j = 0; j < 8; j++) bb[j] = *(const float2*)(bm + j * 8 + 2 * tig);
            #pragma unroll
            for (int t = 0; t < 4; t++) {
                #pragma unroll
                for (int h = 0; h < 2; h++) {
                    int r = wm * 64 + t * 16 + h * 8 + g;
                    int tok = rowTok[r];
                    if (tok >= 0) {
                        float* op = out + (size_t)tok * ODIM_ + nb * 128 + wn * 64;
                        #pragma unroll
                        for (int j = 0; j < 8; j++) {
                            float y0 = acc[t][j][h * 2 + 0] + bb[j].x;
                            float y1 = acc[t][j][h * 2 + 1] + bb[j].y;
                            float2 v;
                            v.x = y0 > 0.f ? y0 : alpha * y0;
                            v.y = y1 > 0.f ? y1 : alpha * y1;
                            *(float2*)(op + j * 8 + 2 * tig) = v;
                        }
                    }
                }
            }
            #pragma unroll
            for (int t = 0; t < 4; t++)
                #pragma unroll
                for (int j = 0; j < 8; j++)
                    #pragma unroll
                    for (int q = 0; q < 4; q++) acc[t][j][q] = 0.f;
        }

        CP_WAIT0();
        __syncthreads();
    }
}

// ---------------------------------------------------------------- launch
extern "C" void kernel_launch(void* const* d_in, const int* in_sizes, int n_in,
                              void* d_out, int out_size) {
    const float* last  = (const float*)d_in[0];
    const float* W     = (const float*)d_in[1];
    const float* bm    = (const float*)d_in[2];
    const float* am    = (const float*)d_in[3];
    const int*   cl    = (const int*)d_in[4];
    const int*   cr    = (const int*)d_in[5];
    const int*   vec   = (const int*)d_in[6];
    const int*   drev  = (const int*)d_in[7];
    const int*   dmap  = (const int*)d_in[8];
    float*       out   = (float*)d_out;

    (void)in_sizes; (void)n_in; (void)out_size;

    static bool attr_done = false;
    if (!attr_done) {
        cudaFuncSetAttribute(k_gemm, cudaFuncAttributeMaxDynamicSharedMemorySize, SMEM_DYN);
        attr_done = true;
    }

    k_prep<<<384, 256>>>(W);
    k_bucket<<<NTOK / 256, 256>>>(cl, cr, vec, drev, dmap);
    k_gemm<<<MAXTILES, 128, SMEM_DYN>>>(last, bm, am, out);
}